// round 3
// baseline (speedup 1.0000x reference)
#include <cuda_runtime.h>

#define D 128
#define N_MAX 100000
#define A_MAX 4096
#define S_MAX 512
#define TEMP_INV 10.0f

// Scratch (allocation-free rule: __device__ globals)
__device__ float2 g_meta[N_MAX];   // .x = 1/||x_row||, .y = (float)y_row
__device__ float  g_loss[A_MAX];   // per-anchor loss

// ---------------------------------------------------------------------------
// Kernel 1: per-row inverse L2 norm + label, packed into one float2.
// One warp per row: 32 lanes x float4 = 128 floats.
// ---------------------------------------------------------------------------
__global__ void meta_kernel(const float* __restrict__ x,
                            const int* __restrict__ y, int N) {
    int row  = blockIdx.x * (blockDim.x >> 5) + (threadIdx.x >> 5);
    int lane = threadIdx.x & 31;
    if (row >= N) return;
    float4 v = __ldg(((const float4*)(x + (size_t)row * D)) + lane);
    float s = v.x * v.x + v.y * v.y + v.z * v.z + v.w * v.w;
#pragma unroll
    for (int o = 16; o > 0; o >>= 1)
        s += __shfl_xor_sync(0xffffffffu, s, o);
    if (lane == 0)
        g_meta[row] = make_float2(rsqrtf(s), (float)__ldg(y + row));
}

// ---------------------------------------------------------------------------
// Kernel 2: one block per anchor. 8 warps x 64 samples.
// Warp-cooperative row gather (float4/lane, 512B coalesced), FMA dot,
// shuffle reduce, lane0 does exp + masked accumulation.
// ---------------------------------------------------------------------------
__global__ __launch_bounds__(256)
void loss_kernel(const float* __restrict__ x,
                 const int* __restrict__ anchors,
                 const int* __restrict__ sampled, int S) {
    __shared__ float4 af[32];       // anchor feature, pre-scaled by inv_norm[a]
    __shared__ int    sidx[S_MAX];  // sampled indices for this anchor
    __shared__ float  s_num[8], s_den[8];
    __shared__ int    s_cnt[8];

    int a    = blockIdx.x;
    int tid  = threadIdx.x;
    int lane = tid & 31;
    int w    = tid >> 5;

    int    aidx = __ldg(anchors + a);
    float2 am   = g_meta[aidx];

    if (tid < 32) {
        float4 v = __ldg(((const float4*)(x + (size_t)aidx * D)) + tid);
        af[tid] = make_float4(v.x * am.x, v.y * am.x, v.z * am.x, v.w * am.x);
    }
    for (int i = tid; i < S; i += blockDim.x)
        sidx[i] = __ldg(sampled + (size_t)a * S + i);
    __syncthreads();

    float4 av = af[lane];
    float  ya = am.y;
    float  num = 0.f, den = 0.f;
    int    cnt = 0;

    int per = S >> 3;        // samples per warp (64 for S=512)
    int s0  = w * per;
#pragma unroll 4
    for (int i = 0; i < per; ++i) {
        int si = sidx[s0 + i];
        float4 v = __ldg(((const float4*)(x + (size_t)si * D)) + lane);
        float p = fmaf(av.x, v.x,
                  fmaf(av.y, v.y,
                  fmaf(av.z, v.z, av.w * v.w)));
#pragma unroll
        for (int o = 16; o > 0; o >>= 1)
            p += __shfl_down_sync(0xffffffffu, p, o);
        if (lane == 0) {
            float2 sm = g_meta[si];
            float  e  = __expf(p * sm.x * TEMP_INV);
            den += e;
            if (sm.y == ya) { num += e; cnt++; }
        }
    }

    if (lane == 0) { s_num[w] = num; s_den[w] = den; s_cnt[w] = cnt; }
    __syncthreads();

    if (tid == 0) {
        float tn = 0.f, td = 0.f; int tc = 0;
#pragma unroll
        for (int i = 0; i < 8; ++i) { tn += s_num[i]; td += s_den[i]; tc += s_cnt[i]; }
        float loss = 0.f;
        if (tc > 0)
            loss = (logf(td) - logf(tn)) / (float)tc;   // = -log(num/den)/cnt
        g_loss[a] = loss;
    }
}

// ---------------------------------------------------------------------------
// Kernel 3: deterministic single-block reduction of per-anchor losses.
// ---------------------------------------------------------------------------
__global__ void reduce_kernel(float* __restrict__ out, int A) {
    __shared__ float sm[256];
    float s = 0.f;
    for (int i = threadIdx.x; i < A; i += 256)
        s += g_loss[i];
    sm[threadIdx.x] = s;
    __syncthreads();
#pragma unroll
    for (int o = 128; o > 0; o >>= 1) {
        if (threadIdx.x < o) sm[threadIdx.x] += sm[threadIdx.x + o];
        __syncthreads();
    }
    if (threadIdx.x == 0) out[0] = sm[0];
}

// ---------------------------------------------------------------------------
extern "C" void kernel_launch(void* const* d_in, const int* in_sizes, int n_in,
                              void* d_out, int out_size) {
    const float* x       = (const float*)d_in[0];
    const int*   y       = (const int*)d_in[1];
    const int*   anchors = (const int*)d_in[2];
    const int*   sampled = (const int*)d_in[3];
    float*       out     = (float*)d_out;

    int N = in_sizes[1];                 // 100000
    int A = in_sizes[2];                 // 4096
    int S = in_sizes[3] / A;             // 512

    // 1) per-node {inv_norm, label} — 8 warps/block -> 8 rows/block
    int rows_per_block = 8;
    int mblocks = (N + rows_per_block - 1) / rows_per_block;
    meta_kernel<<<mblocks, 256>>>(x, y, N);

    // 2) per-anchor loss
    loss_kernel<<<A, 256>>>(x, anchors, sampled, S);

    // 3) final sum
    reduce_kernel<<<1, 256>>>(out, A);
}

// round 4
// speedup vs baseline: 1.5395x; 1.5395x over previous
#include <cuda_runtime.h>
#include <cuda_fp16.h>

#define D 128
#define N_MAX 100000
#define A_MAX 4096
#define S_MAX 512
#define TEMP_INV 10.0f

// Scratch (allocation-free rule: __device__ globals)
// Normalized features, fp16, 256B per row (16 x uint4). 25.6 MB — L2 resident.
__device__ uint4         g_xh[N_MAX * 16];
__device__ unsigned char g_lab[N_MAX];     // labels 0..9
__device__ float         g_loss[A_MAX];

// ---------------------------------------------------------------------------
// Kernel 1: normalize rows -> fp16, store labels. One warp per 2 rows (ILP).
// ---------------------------------------------------------------------------
__global__ __launch_bounds__(256)
void prep_kernel(const float* __restrict__ x,
                 const int* __restrict__ y, int N) {
    int gw   = (blockIdx.x * blockDim.x + threadIdx.x) >> 5;  // global warp id
    int lane = threadIdx.x & 31;
    int row0 = gw * 2;
    if (row0 >= N) return;
    int  row1 = row0 + 1;
    bool has1 = row1 < N;

    float4 v0 = __ldg((const float4*)(x + (size_t)row0 * D) + lane);
    float4 v1 = has1 ? __ldg((const float4*)(x + (size_t)row1 * D) + lane)
                     : make_float4(1.f, 0.f, 0.f, 0.f);

    float s0 = v0.x * v0.x + v0.y * v0.y + v0.z * v0.z + v0.w * v0.w;
    float s1 = v1.x * v1.x + v1.y * v1.y + v1.z * v1.z + v1.w * v1.w;
#pragma unroll
    for (int o = 16; o > 0; o >>= 1) {
        s0 += __shfl_xor_sync(0xffffffffu, s0, o);
        s1 += __shfl_xor_sync(0xffffffffu, s1, o);
    }
    float r0 = rsqrtf(s0);
    float r1 = rsqrtf(s1);

    // pack 4 scaled floats -> 2 half2 -> uint2, store at lane*8B (coalesced)
    __half2 a0 = __floats2half2_rn(v0.x * r0, v0.y * r0);
    __half2 b0 = __floats2half2_rn(v0.z * r0, v0.w * r0);
    uint2 p0 = make_uint2(*(unsigned int*)&a0, *(unsigned int*)&b0);
    ((uint2*)g_xh)[(size_t)row0 * 32 + lane] = p0;

    if (has1) {
        __half2 a1 = __floats2half2_rn(v1.x * r1, v1.y * r1);
        __half2 b1 = __floats2half2_rn(v1.z * r1, v1.w * r1);
        uint2 p1 = make_uint2(*(unsigned int*)&a1, *(unsigned int*)&b1);
        ((uint2*)g_xh)[(size_t)row1 * 32 + lane] = p1;
    }

    if (lane == 0) {
        g_lab[row0] = (unsigned char)__ldg(y + row0);
        if (has1) g_lab[row1] = (unsigned char)__ldg(y + row1);
    }
}

// ---------------------------------------------------------------------------
// Kernel 2: one block per anchor. 8 warps; each warp: 64 samples, 2 at a time
// (16 lanes per sample, uint4 = 8 halves per lane, 4-step xor reduce).
// ---------------------------------------------------------------------------
__global__ __launch_bounds__(256)
void loss_kernel(const int* __restrict__ anchors,
                 const int* __restrict__ sampled, int S) {
    __shared__ float af[D];          // anchor features (normalized, fp32)
    __shared__ int   sidx[S_MAX];
    __shared__ float s_num[8], s_den[8];
    __shared__ int   s_cnt[8];

    int a    = blockIdx.x;
    int tid  = threadIdx.x;
    int lane = tid & 31;
    int w    = tid >> 5;
    int hl   = lane & 15;            // lane within 16-group
    int half = lane >> 4;            // which sample of the pair

    int aidx = __ldg(anchors + a);

    // stage anchor row (fp16 -> fp32) and sample indices
    if (tid < 64) {
        unsigned int u = ((const unsigned int*)g_xh)[(size_t)aidx * 64 + tid];
        float2 f = __half22float2(*(__half2*)&u);
        af[tid * 2]     = f.x;
        af[tid * 2 + 1] = f.y;
    }
    for (int i = tid; i < S; i += blockDim.x)
        sidx[i] = __ldg(sampled + (size_t)a * S + i);
    __syncthreads();

    // per-lane anchor slice: 8 consecutive dims
    float af0 = af[hl * 8 + 0], af1 = af[hl * 8 + 1];
    float af2 = af[hl * 8 + 2], af3 = af[hl * 8 + 3];
    float af4 = af[hl * 8 + 4], af5 = af[hl * 8 + 5];
    float af6 = af[hl * 8 + 6], af7 = af[hl * 8 + 7];

    unsigned char ya = g_lab[aidx];
    float num = 0.f, den = 0.f;
    int   cnt = 0;

    int per = S >> 3;                // 64 samples per warp
    int s0  = w * per;
#pragma unroll 4
    for (int i = 0; i < per; i += 2) {
        int si = sidx[s0 + i + half];
        uint4 v = g_xh[(size_t)si * 16 + hl];
        float2 f0 = __half22float2(*(__half2*)&v.x);
        float2 f1 = __half22float2(*(__half2*)&v.y);
        float2 f2 = __half22float2(*(__half2*)&v.z);
        float2 f3 = __half22float2(*(__half2*)&v.w);
        float p = af0 * f0.x;
        p = fmaf(af1, f0.y, p);
        p = fmaf(af2, f1.x, p);
        p = fmaf(af3, f1.y, p);
        p = fmaf(af4, f2.x, p);
        p = fmaf(af5, f2.y, p);
        p = fmaf(af6, f3.x, p);
        p = fmaf(af7, f3.y, p);
#pragma unroll
        for (int o = 8; o > 0; o >>= 1)
            p += __shfl_xor_sync(0xffffffffu, p, o);
        if (hl == 0) {
            float e = __expf(p * TEMP_INV);
            den += e;
            if (g_lab[si] == ya) { num += e; cnt++; }
        }
    }

    // combine lane 0 and lane 16
    num += __shfl_down_sync(0xffffffffu, num, 16);
    den += __shfl_down_sync(0xffffffffu, den, 16);
    cnt += __shfl_down_sync(0xffffffffu, cnt, 16);
    if (lane == 0) { s_num[w] = num; s_den[w] = den; s_cnt[w] = cnt; }
    __syncthreads();

    if (tid == 0) {
        float tn = 0.f, td = 0.f; int tc = 0;
#pragma unroll
        for (int i = 0; i < 8; ++i) { tn += s_num[i]; td += s_den[i]; tc += s_cnt[i]; }
        float loss = 0.f;
        if (tc > 0)
            loss = (logf(td) - logf(tn)) / (float)tc;   // = -log(num/den)/cnt
        g_loss[a] = loss;
    }
}

// ---------------------------------------------------------------------------
// Kernel 3: deterministic single-block reduction.
// ---------------------------------------------------------------------------
__global__ void reduce_kernel(float* __restrict__ out, int A) {
    __shared__ float sm[256];
    float s = 0.f;
    for (int i = threadIdx.x; i < A; i += 256)
        s += g_loss[i];
    sm[threadIdx.x] = s;
    __syncthreads();
#pragma unroll
    for (int o = 128; o > 0; o >>= 1) {
        if (threadIdx.x < o) sm[threadIdx.x] += sm[threadIdx.x + o];
        __syncthreads();
    }
    if (threadIdx.x == 0) out[0] = sm[0];
}

// ---------------------------------------------------------------------------
extern "C" void kernel_launch(void* const* d_in, const int* in_sizes, int n_in,
                              void* d_out, int out_size) {
    const float* x       = (const float*)d_in[0];
    const int*   y       = (const int*)d_in[1];
    const int*   anchors = (const int*)d_in[2];
    const int*   sampled = (const int*)d_in[3];
    float*       out     = (float*)d_out;

    int N = in_sizes[1];                 // 100000
    int A = in_sizes[2];                 // 4096
    int S = in_sizes[3] / A;             // 512

    // 1) normalize -> fp16 + labels (16 rows per 256-thread block)
    int rows_per_block = 16;
    int pblocks = (N + rows_per_block - 1) / rows_per_block;
    prep_kernel<<<pblocks, 256>>>(x, y, N);

    // 2) per-anchor loss
    loss_kernel<<<A, 256>>>(anchors, sampled, S);

    // 3) final sum
    reduce_kernel<<<1, 256>>>(out, A);
}

// round 5
// speedup vs baseline: 2.3636x; 1.5353x over previous
#include <cuda_runtime.h>
#include <cuda_fp16.h>
#include <cuda_fp8.h>

#define D 128
#define N_MAX 100000
#define A_MAX 4096
#define S_MAX 512
#define TEMP_INV 10.0f

// Scratch (allocation-free rule: __device__ globals)
// Normalized features, fp8 e4m3: 128 B per row = 8 x uint4. 12.8 MB — L2 resident.
__device__ uint4         g_x8[N_MAX * 8];
__device__ unsigned char g_lab[N_MAX];     // labels 0..9
__device__ float         g_loss[A_MAX];

__device__ __forceinline__ __half2 fp8x2_to_h2(unsigned short v) {
    __half2_raw r = __nv_cvt_fp8x2_to_halfraw2((__nv_fp8x2_storage_t)v, __NV_E4M3);
    return *reinterpret_cast<__half2*>(&r);
}
__device__ __forceinline__ unsigned short f2_to_fp8x2(float a, float b) {
    return (unsigned short)__nv_cvt_float2_to_fp8x2(make_float2(a, b),
                                                    __NV_SATFINITE, __NV_E4M3);
}

// ---------------------------------------------------------------------------
// Kernel 1: normalize rows -> fp8 e4m3, store labels. One warp per 2 rows.
// ---------------------------------------------------------------------------
__global__ __launch_bounds__(256)
void prep_kernel(const float* __restrict__ x,
                 const int* __restrict__ y, int N) {
    int gw   = (blockIdx.x * blockDim.x + threadIdx.x) >> 5;
    int lane = threadIdx.x & 31;
    int row0 = gw * 2;
    if (row0 >= N) return;
    int  row1 = row0 + 1;
    bool has1 = row1 < N;

    float4 v0 = __ldg((const float4*)(x + (size_t)row0 * D) + lane);
    float4 v1 = has1 ? __ldg((const float4*)(x + (size_t)row1 * D) + lane)
                     : make_float4(1.f, 0.f, 0.f, 0.f);

    float s0 = v0.x * v0.x + v0.y * v0.y + v0.z * v0.z + v0.w * v0.w;
    float s1 = v1.x * v1.x + v1.y * v1.y + v1.z * v1.z + v1.w * v1.w;
#pragma unroll
    for (int o = 16; o > 0; o >>= 1) {
        s0 += __shfl_xor_sync(0xffffffffu, s0, o);
        s1 += __shfl_xor_sync(0xffffffffu, s1, o);
    }
    float r0 = rsqrtf(s0);
    float r1 = rsqrtf(s1);

    // 4 floats -> 4 fp8 -> one uint, store at lane*4B (coalesced 128B/row)
    unsigned int p0 = (unsigned int)f2_to_fp8x2(v0.x * r0, v0.y * r0)
                    | ((unsigned int)f2_to_fp8x2(v0.z * r0, v0.w * r0) << 16);
    ((unsigned int*)g_x8)[(size_t)row0 * 32 + lane] = p0;
    if (has1) {
        unsigned int p1 = (unsigned int)f2_to_fp8x2(v1.x * r1, v1.y * r1)
                        | ((unsigned int)f2_to_fp8x2(v1.z * r1, v1.w * r1) << 16);
        ((unsigned int*)g_x8)[(size_t)row1 * 32 + lane] = p1;
    }

    if (lane == 0) {
        g_lab[row0] = (unsigned char)__ldg(y + row0);
        if (has1) g_lab[row1] = (unsigned char)__ldg(y + row1);
    }
}

// ---------------------------------------------------------------------------
// Kernel 2: one block per anchor. 8 warps; each warp: 64 samples, 4 at a time.
// 8 lanes per sample, uint4 = 16 fp8 per lane, HFMA2 dot, 3-step xor reduce.
// ---------------------------------------------------------------------------
__global__ __launch_bounds__(256)
void loss_kernel(const int* __restrict__ anchors,
                 const int* __restrict__ sampled, int S) {
    __shared__ __half2 af[64];       // anchor row as 64 half2 (128 halves)
    __shared__ int     sidx[S_MAX];
    __shared__ float   s_num[8], s_den[8];
    __shared__ int     s_cnt[8];

    int a    = blockIdx.x;
    int tid  = threadIdx.x;
    int lane = tid & 31;
    int w    = tid >> 5;
    int hl   = lane & 7;             // lane within 8-group
    int sub  = lane >> 3;            // which of 4 samples

    int aidx = __ldg(anchors + a);

    // stage anchor row (fp8 -> half2) and sample indices
    if (tid < 32) {
        unsigned int u = ((const unsigned int*)g_x8)[(size_t)aidx * 32 + tid];
        af[tid * 2]     = fp8x2_to_h2((unsigned short)(u & 0xffffu));
        af[tid * 2 + 1] = fp8x2_to_h2((unsigned short)(u >> 16));
    }
    for (int i = tid; i < S; i += blockDim.x)
        sidx[i] = __ldg(sampled + (size_t)a * S + i);
    __syncthreads();

    // per-lane anchor slice: 16 consecutive dims = 8 half2
    __half2 a0 = af[hl * 8 + 0], a1 = af[hl * 8 + 1];
    __half2 a2 = af[hl * 8 + 2], a3 = af[hl * 8 + 3];
    __half2 a4 = af[hl * 8 + 4], a5 = af[hl * 8 + 5];
    __half2 a6 = af[hl * 8 + 6], a7 = af[hl * 8 + 7];

    unsigned char ya = g_lab[aidx];
    float num = 0.f, den = 0.f;
    int   cnt = 0;

    int per = S >> 3;                // 64 samples per warp
    int s0  = w * per;
#pragma unroll 4
    for (int i = 0; i < per; i += 4) {
        int si = sidx[s0 + i + sub];
        uint4 v = g_x8[(size_t)si * 8 + hl];    // 16 B = 16 fp8
        __half2 acc;
        acc = __hmul2(a0, fp8x2_to_h2((unsigned short)(v.x & 0xffffu)));
        acc = __hfma2(a1, fp8x2_to_h2((unsigned short)(v.x >> 16)), acc);
        acc = __hfma2(a2, fp8x2_to_h2((unsigned short)(v.y & 0xffffu)), acc);
        acc = __hfma2(a3, fp8x2_to_h2((unsigned short)(v.y >> 16)), acc);
        acc = __hfma2(a4, fp8x2_to_h2((unsigned short)(v.z & 0xffffu)), acc);
        acc = __hfma2(a5, fp8x2_to_h2((unsigned short)(v.z >> 16)), acc);
        acc = __hfma2(a6, fp8x2_to_h2((unsigned short)(v.w & 0xffffu)), acc);
        acc = __hfma2(a7, fp8x2_to_h2((unsigned short)(v.w >> 16)), acc);
        float2 f = __half22float2(acc);
        float  p = f.x + f.y;
#pragma unroll
        for (int o = 4; o > 0; o >>= 1)
            p += __shfl_xor_sync(0xffffffffu, p, o);
        if (hl == 0) {
            float e = __expf(p * TEMP_INV);
            den += e;
            if (g_lab[si] == ya) { num += e; cnt++; }
        }
    }

    // combine the 4 sub-lanes (0,8,16,24); other lanes carry zeros
    num += __shfl_xor_sync(0xffffffffu, num, 8);
    den += __shfl_xor_sync(0xffffffffu, den, 8);
    cnt += __shfl_xor_sync(0xffffffffu, cnt, 8);
    num += __shfl_xor_sync(0xffffffffu, num, 16);
    den += __shfl_xor_sync(0xffffffffu, den, 16);
    cnt += __shfl_xor_sync(0xffffffffu, cnt, 16);
    if (lane == 0) { s_num[w] = num; s_den[w] = den; s_cnt[w] = cnt; }
    __syncthreads();

    if (tid == 0) {
        float tn = 0.f, td = 0.f; int tc = 0;
#pragma unroll
        for (int i = 0; i < 8; ++i) { tn += s_num[i]; td += s_den[i]; tc += s_cnt[i]; }
        float loss = 0.f;
        if (tc > 0)
            loss = (logf(td) - logf(tn)) / (float)tc;   // = -log(num/den)/cnt
        g_loss[a] = loss;
    }
}

// ---------------------------------------------------------------------------
// Kernel 3: deterministic single-block reduction.
// ---------------------------------------------------------------------------
__global__ void reduce_kernel(float* __restrict__ out, int A) {
    __shared__ float sm[256];
    float s = 0.f;
    for (int i = threadIdx.x; i < A; i += 256)
        s += g_loss[i];
    sm[threadIdx.x] = s;
    __syncthreads();
#pragma unroll
    for (int o = 128; o > 0; o >>= 1) {
        if (threadIdx.x < o) sm[threadIdx.x] += sm[threadIdx.x + o];
        __syncthreads();
    }
    if (threadIdx.x == 0) out[0] = sm[0];
}

// ---------------------------------------------------------------------------
extern "C" void kernel_launch(void* const* d_in, const int* in_sizes, int n_in,
                              void* d_out, int out_size) {
    const float* x       = (const float*)d_in[0];
    const int*   y       = (const int*)d_in[1];
    const int*   anchors = (const int*)d_in[2];
    const int*   sampled = (const int*)d_in[3];
    float*       out     = (float*)d_out;

    int N = in_sizes[1];                 // 100000
    int A = in_sizes[2];                 // 4096
    int S = in_sizes[3] / A;             // 512

    // 1) normalize -> fp8 + labels (16 rows per 256-thread block)
    int rows_per_block = 16;
    int pblocks = (N + rows_per_block - 1) / rows_per_block;
    prep_kernel<<<pblocks, 256>>>(x, y, N);

    // 2) per-anchor loss
    loss_kernel<<<A, 256>>>(anchors, sampled, S);

    // 3) final sum
    reduce_kernel<<<1, 256>>>(out, A);
}